// round 4
// baseline (speedup 1.0000x reference)
#include <cuda_runtime.h>
#include <math.h>
#include <stdint.h>

// ---------------------------------------------------------------------------
// GAT (3-layer) on GB300.  N=50000 nodes, E=800000 edges (+N self loops).
// L1: 256 -> 64x8 (relu), L2: 512 -> 64x8 (relu), L3: 512 -> 47, log_softmax.
// ---------------------------------------------------------------------------

#define MAXN 50000
#define MAXE 800000
#define MAXET (MAXE + MAXN)

// Scratch (static device globals; allocation APIs are banned)
__device__ __align__(16) float g_h[(size_t)MAXN * 512];     // X @ W        (102.4 MB)
__device__ __align__(16) float g_feat[(size_t)MAXN * 512];  // layer input  (102.4 MB)
__device__ __align__(16) float g_out[(size_t)MAXN * 512];   // aggregation  (102.4 MB)
__device__ __align__(16) float g_elog[(size_t)MAXET * 8];   // edge logits / exp (27.2 MB)
__device__ float g_als[MAXN * 8];
__device__ float g_ald[MAXN * 8];
__device__ float g_max[MAXN * 8];
__device__ float g_den[MAXN * 8];   // sum, then reciprocal after inv pass

// ---------------------------------------------------------------------------
// Big-tile GEMM for N % 128 == 0, K % 16 == 0:
//   C[M,N] = A[M,K] @ B[K,N], 128x128 tile, 8x8 microtile, 256 threads.
// ---------------------------------------------------------------------------
__global__ __launch_bounds__(256, 2) void gemm128_kernel(
        const float* __restrict__ Aext, int useFeat,
        const float* __restrict__ B,
        int M, int K, int N) {
    const float* A = useFeat ? g_feat : Aext;
    __shared__ float As[16][132];   // [k][m], pad 4 floats keeps 16B alignment
    __shared__ float Bs[16][128];   // [k][n]
    int tid = threadIdx.x;
    int tx = tid & 15, ty = tid >> 4;
    int bm = blockIdx.y * 128, bn = blockIdx.x * 128;

    float acc[8][8] = {};

    for (int k0 = 0; k0 < K; k0 += 16) {
        #pragma unroll
        for (int l = 0; l < 2; l++) {
            int f = tid * 2 + l;
            int row = f >> 2, kq = f & 3;       // row 0..127, k-quarter 0..3
            int gm = bm + row;
            float4 v = make_float4(0.f, 0.f, 0.f, 0.f);
            if (gm < M) v = *(const float4*)(A + (size_t)gm * K + k0 + kq * 4);
            As[kq * 4 + 0][row] = v.x;
            As[kq * 4 + 1][row] = v.y;
            As[kq * 4 + 2][row] = v.z;
            As[kq * 4 + 3][row] = v.w;
        }
        #pragma unroll
        for (int l = 0; l < 2; l++) {
            int f = tid * 2 + l;
            int kk = f >> 5, nq = f & 31;
            float4 v = *(const float4*)(B + (size_t)(k0 + kk) * N + bn + nq * 4);
            *(float4*)&Bs[kk][nq * 4] = v;
        }
        __syncthreads();

        #pragma unroll
        for (int kk = 0; kk < 16; kk++) {
            float4 a0 = *(const float4*)&As[kk][ty * 8];
            float4 a1 = *(const float4*)&As[kk][ty * 8 + 4];
            float4 b0 = *(const float4*)&Bs[kk][tx * 8];
            float4 b1 = *(const float4*)&Bs[kk][tx * 8 + 4];
            float a[8] = {a0.x, a0.y, a0.z, a0.w, a1.x, a1.y, a1.z, a1.w};
            float b[8] = {b0.x, b0.y, b0.z, b0.w, b1.x, b1.y, b1.z, b1.w};
            #pragma unroll
            for (int i = 0; i < 8; i++)
                #pragma unroll
                for (int j = 0; j < 8; j++)
                    acc[i][j] += a[i] * b[j];
        }
        __syncthreads();
    }

    #pragma unroll
    for (int i = 0; i < 8; i++) {
        int gm = bm + ty * 8 + i;
        if (gm >= M) continue;
        float* cp = g_h + (size_t)gm * N + bn + tx * 8;
        *(float4*)cp       = make_float4(acc[i][0], acc[i][1], acc[i][2], acc[i][3]);
        *(float4*)(cp + 4) = make_float4(acc[i][4], acc[i][5], acc[i][6], acc[i][7]);
    }
}

// ---------------------------------------------------------------------------
// Small GEMM (any N):  64x64 tile, 4x4 microtile.  Used for layer 3 (N=47).
// ---------------------------------------------------------------------------
#define BM 64
#define BN 64
#define BK 16

__global__ __launch_bounds__(256) void gemm_kernel(
        const float* __restrict__ Aext, int useFeat,
        const float* __restrict__ B,
        int M, int K, int N) {
    const float* A = useFeat ? g_feat : Aext;
    __shared__ float As[BK][BM + 4];
    __shared__ float Bs[BK][BN];
    int tid = threadIdx.x;
    int tx = tid & 15, ty = tid >> 4;
    int bm = blockIdx.y * BM, bn = blockIdx.x * BN;
    float acc[4][4] = {};

    for (int k0 = 0; k0 < K; k0 += BK) {
        #pragma unroll
        for (int i = tid; i < BM * BK; i += 256) {
            int m = i >> 4, kk = i & 15;
            int gm = bm + m;
            As[kk][m] = (gm < M) ? A[(size_t)gm * K + (k0 + kk)] : 0.f;
        }
        #pragma unroll
        for (int i = tid; i < BK * BN; i += 256) {
            int kk = i >> 6, n = i & 63;
            int gn = bn + n;
            Bs[kk][n] = (gn < N) ? B[(size_t)(k0 + kk) * N + gn] : 0.f;
        }
        __syncthreads();
        #pragma unroll
        for (int kk = 0; kk < BK; kk++) {
            float a[4], b[4];
            #pragma unroll
            for (int i = 0; i < 4; i++) a[i] = As[kk][ty * 4 + i];
            #pragma unroll
            for (int j = 0; j < 4; j++) b[j] = Bs[kk][tx * 4 + j];
            #pragma unroll
            for (int i = 0; i < 4; i++)
                #pragma unroll
                for (int j = 0; j < 4; j++)
                    acc[i][j] += a[i] * b[j];
        }
        __syncthreads();
    }

    #pragma unroll
    for (int i = 0; i < 4; i++) {
        int gm = bm + ty * 4 + i;
        if (gm >= M) continue;
        #pragma unroll
        for (int j = 0; j < 4; j++) {
            int gn = bn + tx * 4 + j;
            if (gn < N) g_h[(size_t)gm * N + gn] = acc[i][j];
        }
    }
}

// ---------------------------------------------------------------------------
// Per-node attention dots + init of segment-softmax accumulators.
// ---------------------------------------------------------------------------
template <int H, int C>
__global__ void node_alpha_kernel(const float* __restrict__ a_src,
                                  const float* __restrict__ a_dst, int N) {
    int i = blockIdx.x * blockDim.x + threadIdx.x;
    if (i >= N * H) return;
    int n = i / H, hd = i - (i / H) * H;
    const float* hp = g_h + (size_t)n * (H * C) + hd * C;
    float s = 0.f, d = 0.f;
    #pragma unroll 8
    for (int c = 0; c < C; c++) {
        float v = hp[c];
        s += v * a_src[hd * C + c];
        d += v * a_dst[hd * C + c];
    }
    g_als[i] = s;
    g_ald[i] = d;
    g_max[i] = -INFINITY;
    g_den[i] = 0.f;
}

// float atomic max via sign-split int trick (canonicalize -0 first)
__device__ __forceinline__ void atomicMaxF(float* addr, float v) {
    v += 0.0f;  // -0 -> +0
    if (v >= 0.f) atomicMax((int*)addr, __float_as_int(v));
    else          atomicMin((unsigned int*)addr, __float_as_uint(v));
}

// ---------------------------------------------------------------------------
// Edge pass 1: e = leaky_relu(als[src]+ald[dst]); store; segment max on dst.
// Edges [0,E) from edge_index; edges [E,E+N) are self loops.
// ---------------------------------------------------------------------------
template <int H>
__global__ void edge_max_kernel(const int* __restrict__ src,
                                const int* __restrict__ dst, int E, int N) {
    int i = blockIdx.x * blockDim.x + threadIdx.x;
    int tot = (E + N) * H;
    if (i >= tot) return;
    int e = i / H, hd = i - e * H;
    int s, d;
    if (e < E) { s = src[e]; d = dst[e]; } else { s = d = e - E; }
    float v = g_als[s * H + hd] + g_ald[d * H + hd];
    v = (v > 0.f) ? v : 0.2f * v;
    g_elog[i] = v;
    atomicMaxF(&g_max[d * H + hd], v);
}

// Edge pass 2: ex = exp(e - max[dst]); store; segment sum on dst.
template <int H>
__global__ void edge_expsum_kernel(const int* __restrict__ dst, int E, int N) {
    int i = blockIdx.x * blockDim.x + threadIdx.x;
    int tot = (E + N) * H;
    if (i >= tot) return;
    int e = i / H, hd = i - e * H;
    int d = (e < E) ? dst[e] : e - E;
    float ex = __expf(g_elog[i] - g_max[d * H + hd]);
    g_elog[i] = ex;
    atomicAdd(&g_den[d * H + hd], ex);
}

// den -> 1/(den + 1e-16), once per (node, head).  Removes per-edge divisions.
__global__ void inv_den_kernel(int n) {
    int i = blockIdx.x * blockDim.x + threadIdx.x;
    if (i < n) g_den[i] = 1.f / (g_den[i] + 1e-16f);
}

__global__ void zero_kernel(size_t n) {
    size_t i = (size_t)blockIdx.x * blockDim.x + threadIdx.x;
    if (i < n) g_out[i] = 0.f;
}

// ---------------------------------------------------------------------------
// Aggregation (H=8, C=64): one warp per edge.  4 lanes per head, 16 channels
// per lane.  out[dst] += alpha * h[src] via red.global.add.v4.f32.
// ---------------------------------------------------------------------------
__device__ __forceinline__ void red4(float* addr, float a, float b, float c, float d) {
    asm volatile("red.global.add.v4.f32 [%0], {%1,%2,%3,%4};"
                 :: "l"(addr), "f"(a), "f"(b), "f"(c), "f"(d) : "memory");
}

__global__ void aggregate_wide_kernel(const int* __restrict__ src,
                                      const int* __restrict__ dst, int E, int N) {
    int w = (blockIdx.x * blockDim.x + threadIdx.x) >> 5;
    int lane = threadIdx.x & 31;
    int tot = E + N;
    if (w >= tot) return;
    int s, d;
    if (w < E) { s = src[w]; d = dst[w]; } else { s = d = w - E; }
    int hd = lane >> 2;  // head for this lane's 16 channels
    float c = g_elog[(size_t)w * 8 + hd] * g_den[d * 8 + hd];   // den holds reciprocal
    const float4* hp = (const float4*)(g_h + (size_t)s * 512 + lane * 16);
    float* op = g_out + (size_t)d * 512 + lane * 16;
    #pragma unroll
    for (int j = 0; j < 4; j++) {
        float4 v = hp[j];
        red4(op + j * 4, c * v.x, c * v.y, c * v.z, c * v.w);
    }
}

// Aggregation for layer 3 (H=1, C=47): one warp per edge, scalar atomics.
__global__ void aggregate_narrow_kernel(const int* __restrict__ src,
                                        const int* __restrict__ dst, int E, int N) {
    int w = (blockIdx.x * blockDim.x + threadIdx.x) >> 5;
    int lane = threadIdx.x & 31;
    int tot = E + N;
    if (w >= tot) return;
    int s, d;
    if (w < E) { s = src[w]; d = dst[w]; } else { s = d = w - E; }
    float c = g_elog[w] * g_den[d];   // den holds reciprocal
    for (int ch = lane; ch < 47; ch += 32)
        atomicAdd(&g_out[(size_t)d * 47 + ch], c * g_h[(size_t)s * 47 + ch]);
}

// feat = relu(out + bias)   (layers 1 & 2 epilogue; HC = 512, power of two)
__global__ void bias_relu_kernel(const float* __restrict__ bias, int N, int HC) {
    unsigned i = blockIdx.x * blockDim.x + threadIdx.x;
    if (i >= (unsigned)(N * HC)) return;
    g_feat[i] = fmaxf(g_out[i] + bias[i & (unsigned)(HC - 1)], 0.f);
}

// layer 3 epilogue: logits = out + bias; row log_softmax over 47 classes.
__global__ void logsoftmax_kernel(const float* __restrict__ bias,
                                  float* __restrict__ out, int N) {
    int w = (blockIdx.x * blockDim.x + threadIdx.x) >> 5;
    int lane = threadIdx.x & 31;
    if (w >= N) return;
    float v1 = (lane < 47)      ? g_out[(size_t)w * 47 + lane]      + bias[lane]      : -INFINITY;
    float v2 = (lane + 32 < 47) ? g_out[(size_t)w * 47 + lane + 32] + bias[lane + 32] : -INFINITY;
    float m = fmaxf(v1, v2);
    #pragma unroll
    for (int o = 16; o > 0; o >>= 1) m = fmaxf(m, __shfl_xor_sync(0xffffffffu, m, o));
    float sm = ((lane < 47) ? __expf(v1 - m) : 0.f) +
               ((lane + 32 < 47) ? __expf(v2 - m) : 0.f);
    #pragma unroll
    for (int o = 16; o > 0; o >>= 1) sm += __shfl_xor_sync(0xffffffffu, sm, o);
    float lse = m + logf(sm);
    if (lane < 47)      out[(size_t)w * 47 + lane]      = v1 - lse;
    if (lane + 32 < 47) out[(size_t)w * 47 + lane + 32] = v2 - lse;
}

// ---------------------------------------------------------------------------
extern "C" void kernel_launch(void* const* d_in, const int* in_sizes, int n_in,
                              void* d_out, int out_size) {
    const float* x   = (const float*)d_in[0];
    const int*   ei  = (const int*)d_in[1];
    const float* W1  = (const float*)d_in[2];
    const float* as1 = (const float*)d_in[3];
    const float* ad1 = (const float*)d_in[4];
    const float* b1  = (const float*)d_in[5];
    const float* W2  = (const float*)d_in[6];
    const float* as2 = (const float*)d_in[7];
    const float* ad2 = (const float*)d_in[8];
    const float* b2  = (const float*)d_in[9];
    const float* W3  = (const float*)d_in[10];
    const float* as3 = (const float*)d_in[11];
    const float* ad3 = (const float*)d_in[12];
    const float* b3  = (const float*)d_in[13];
    float* out = (float*)d_out;

    int N = in_sizes[0] / 256;   // 50000
    int E = in_sizes[1] / 2;     // 800000
    const int* srcI = ei;
    const int* dstI = ei + E;
    int ET = E + N;

    dim3 grid512(512 / 128, (N + 127) / 128);            // big-tile GEMM, N=512
    dim3 grid47((47 + BN - 1) / BN, (N + BM - 1) / BM);  // small GEMM, N=47
    int eh8 = (ET * 8 + 255) / 256;
    int eh1 = (ET + 255) / 256;
    int aggB = ((size_t)ET * 32 + 255) / 256;

    // ---- Layer 1: 256 -> 64x8, relu ----
    gemm128_kernel<<<grid512, 256>>>(x, 0, W1, N, 256, 512);
    node_alpha_kernel<8, 64><<<(N * 8 + 255) / 256, 256>>>(as1, ad1, N);
    zero_kernel<<<(unsigned)(((size_t)N * 512 + 255) / 256), 256>>>((size_t)N * 512);
    edge_max_kernel<8><<<eh8, 256>>>(srcI, dstI, E, N);
    edge_expsum_kernel<8><<<eh8, 256>>>(dstI, E, N);
    inv_den_kernel<<<(N * 8 + 255) / 256, 256>>>(N * 8);
    aggregate_wide_kernel<<<aggB, 256>>>(srcI, dstI, E, N);
    bias_relu_kernel<<<(N * 512 + 255) / 256, 256>>>(b1, N, 512);

    // ---- Layer 2: 512 -> 64x8, relu ----
    gemm128_kernel<<<grid512, 256>>>(nullptr, 1, W2, N, 512, 512);
    node_alpha_kernel<8, 64><<<(N * 8 + 255) / 256, 256>>>(as2, ad2, N);
    zero_kernel<<<(unsigned)(((size_t)N * 512 + 255) / 256), 256>>>((size_t)N * 512);
    edge_max_kernel<8><<<eh8, 256>>>(srcI, dstI, E, N);
    edge_expsum_kernel<8><<<eh8, 256>>>(dstI, E, N);
    inv_den_kernel<<<(N * 8 + 255) / 256, 256>>>(N * 8);
    aggregate_wide_kernel<<<aggB, 256>>>(srcI, dstI, E, N);
    bias_relu_kernel<<<(N * 512 + 255) / 256, 256>>>(b2, N, 512);

    // ---- Layer 3: 512 -> 47, log_softmax ----
    gemm_kernel<<<grid47, 256>>>(nullptr, 1, W3, N, 512, 47);
    node_alpha_kernel<1, 47><<<(N + 255) / 256, 256>>>(as3, ad3, N);
    zero_kernel<<<(unsigned)(((size_t)N * 47 + 255) / 256), 256>>>((size_t)N * 47);
    edge_max_kernel<1><<<eh1, 256>>>(srcI, dstI, E, N);
    edge_expsum_kernel<1><<<eh1, 256>>>(dstI, E, N);
    inv_den_kernel<<<(N + 255) / 256, 256>>>(N);
    aggregate_narrow_kernel<<<aggB, 256>>>(srcI, dstI, E, N);
    logsoftmax_kernel<<<(N * 32 + 255) / 256, 256>>>(b3, out, N);
}

// round 15
// speedup vs baseline: 1.7544x; 1.7544x over previous
#include <cuda_runtime.h>
#include <math.h>
#include <stdint.h>

// ---------------------------------------------------------------------------
// GAT (3-layer) on GB300.  N=50000 nodes, E=800000 edges (+N self loops).
// L1: 256 -> 64x8 (relu), L2: 512 -> 64x8 (relu), L3: 512 -> 47, log_softmax.
// CSR-by-dst edge phase; ONLINE softmax + aggregation fused per node (no edge
// buffer, no atomics in the per-layer path).  GEMMs: double-buffered 128x128
// (wide) and 128x64 8x4-microtile (layer 3, N=47 guarded).
// ---------------------------------------------------------------------------

#define MAXN 50000
#define MAXE 800000
#define MAXET (MAXE + MAXN)
#define NEG_BIG (-3.0e38f)

__device__ __align__(16) float g_h[(size_t)MAXN * 512];     // X @ W
__device__ __align__(16) float g_feat[(size_t)MAXN * 512];  // layer input
__device__ float g_als[MAXN * 8];
__device__ float g_ald[MAXN * 8];
__device__ int   g_srcCSR[MAXET];       // src node per CSR slot
__device__ int   g_rowptr[MAXN + 1];
__device__ int   g_cnt[MAXN];
__device__ int   g_cur[MAXN];

// Select arr[k] (k in 0..7 runtime-uniform per lane) without local-mem spill.
__device__ __forceinline__ float sel8(const float* a, int k) {
    float r = a[0];
    #pragma unroll
    for (int j = 1; j < 8; j++) r = (k == j) ? a[j] : r;
    return r;
}

// ---------------------------------------------------------------------------
// Big-tile GEMM (N%128==0, K%16==0): 128x128 tile, 8x8 microtile, 256 thr,
// double-buffered smem (prefetch tile t+1 while computing tile t).
// ---------------------------------------------------------------------------
__global__ __launch_bounds__(256, 2) void gemm128_kernel(
        const float* __restrict__ Aext, int useFeat,
        const float* __restrict__ B,
        int M, int K, int N) {
    const float* A = useFeat ? g_feat : Aext;
    __shared__ float As[2][16][132];
    __shared__ float Bs[2][16][128];
    int tid = threadIdx.x;
    int tx = tid & 15, ty = tid >> 4;
    int bm = blockIdx.y * 128, bn = blockIdx.x * 128;

    int af0 = tid * 2,     af1 = tid * 2 + 1;
    int arow0 = af0 >> 2,  akq0 = af0 & 3;
    int arow1 = af1 >> 2,  akq1 = af1 & 3;
    int bkk0 = af0 >> 5,   bnq0 = af0 & 31;
    int bkk1 = af1 >> 5,   bnq1 = af1 & 31;

    float acc[8][8] = {};

    {
        float4 v0 = make_float4(0.f, 0.f, 0.f, 0.f), v1 = v0;
        if (bm + arow0 < M) v0 = *(const float4*)(A + (size_t)(bm + arow0) * K + akq0 * 4);
        if (bm + arow1 < M) v1 = *(const float4*)(A + (size_t)(bm + arow1) * K + akq1 * 4);
        As[0][akq0 * 4 + 0][arow0] = v0.x;  As[0][akq0 * 4 + 1][arow0] = v0.y;
        As[0][akq0 * 4 + 2][arow0] = v0.z;  As[0][akq0 * 4 + 3][arow0] = v0.w;
        As[0][akq1 * 4 + 0][arow1] = v1.x;  As[0][akq1 * 4 + 1][arow1] = v1.y;
        As[0][akq1 * 4 + 2][arow1] = v1.z;  As[0][akq1 * 4 + 3][arow1] = v1.w;
        float4 w0 = *(const float4*)(B + (size_t)bkk0 * N + bn + bnq0 * 4);
        float4 w1 = *(const float4*)(B + (size_t)bkk1 * N + bn + bnq1 * 4);
        *(float4*)&Bs[0][bkk0][bnq0 * 4] = w0;
        *(float4*)&Bs[0][bkk1][bnq1 * 4] = w1;
    }
    __syncthreads();

    int nt = K / 16;
    for (int t = 0; t < nt; t++) {
        int cur = t & 1;
        if (t + 1 < nt) {
            int nxt = cur ^ 1;
            int k0 = (t + 1) * 16;
            float4 v0 = make_float4(0.f, 0.f, 0.f, 0.f), v1 = v0;
            if (bm + arow0 < M) v0 = *(const float4*)(A + (size_t)(bm + arow0) * K + k0 + akq0 * 4);
            if (bm + arow1 < M) v1 = *(const float4*)(A + (size_t)(bm + arow1) * K + k0 + akq1 * 4);
            As[nxt][akq0 * 4 + 0][arow0] = v0.x;  As[nxt][akq0 * 4 + 1][arow0] = v0.y;
            As[nxt][akq0 * 4 + 2][arow0] = v0.z;  As[nxt][akq0 * 4 + 3][arow0] = v0.w;
            As[nxt][akq1 * 4 + 0][arow1] = v1.x;  As[nxt][akq1 * 4 + 1][arow1] = v1.y;
            As[nxt][akq1 * 4 + 2][arow1] = v1.z;  As[nxt][akq1 * 4 + 3][arow1] = v1.w;
            float4 w0 = *(const float4*)(B + (size_t)(k0 + bkk0) * N + bn + bnq0 * 4);
            float4 w1 = *(const float4*)(B + (size_t)(k0 + bkk1) * N + bn + bnq1 * 4);
            *(float4*)&Bs[nxt][bkk0][bnq0 * 4] = w0;
            *(float4*)&Bs[nxt][bkk1][bnq1 * 4] = w1;
        }
        #pragma unroll
        for (int kk = 0; kk < 16; kk++) {
            float4 a0 = *(const float4*)&As[cur][kk][ty * 8];
            float4 a1 = *(const float4*)&As[cur][kk][ty * 8 + 4];
            float4 b0 = *(const float4*)&Bs[cur][kk][tx * 8];
            float4 b1 = *(const float4*)&Bs[cur][kk][tx * 8 + 4];
            float a[8] = {a0.x, a0.y, a0.z, a0.w, a1.x, a1.y, a1.z, a1.w};
            float b[8] = {b0.x, b0.y, b0.z, b0.w, b1.x, b1.y, b1.z, b1.w};
            #pragma unroll
            for (int i = 0; i < 8; i++)
                #pragma unroll
                for (int j = 0; j < 8; j++)
                    acc[i][j] += a[i] * b[j];
        }
        __syncthreads();
    }

    #pragma unroll
    for (int i = 0; i < 8; i++) {
        int gm = bm + ty * 8 + i;
        if (gm >= M) continue;
        float* cp = g_h + (size_t)gm * N + bn + tx * 8;
        *(float4*)cp       = make_float4(acc[i][0], acc[i][1], acc[i][2], acc[i][3]);
        *(float4*)(cp + 4) = make_float4(acc[i][4], acc[i][5], acc[i][6], acc[i][7]);
    }
}

// ---------------------------------------------------------------------------
// Small-N GEMM (layer 3, N=47): 128x64 tile, 8x4 microtile, 256 threads.
// 3 LDS.128 per 32 FMA.  B tile zero-filled beyond N; stores guarded.
// ---------------------------------------------------------------------------
__global__ __launch_bounds__(256) void gemm_small_kernel(
        const float* __restrict__ B, int M, int K, int N) {
    const float* A = g_feat;
    __shared__ float As[16][132];   // [k][m], padded
    __shared__ float Bs[16][64];
    int tid = threadIdx.x;
    int tx = tid & 15, ty = tid >> 4;
    int bm = blockIdx.y * 128, bn = blockIdx.x * 64;
    float acc[8][4] = {};

    for (int k0 = 0; k0 < K; k0 += 16) {
        #pragma unroll
        for (int l = 0; l < 2; l++) {
            int f = tid * 2 + l;
            int row = f >> 2, kq = f & 3;
            int gm = bm + row;
            float4 v = make_float4(0.f, 0.f, 0.f, 0.f);
            if (gm < M) v = *(const float4*)(A + (size_t)gm * K + k0 + kq * 4);
            As[kq * 4 + 0][row] = v.x;
            As[kq * 4 + 1][row] = v.y;
            As[kq * 4 + 2][row] = v.z;
            As[kq * 4 + 3][row] = v.w;
        }
        #pragma unroll
        for (int l = 0; l < 4; l++) {
            int i = tid + l * 256;
            int kk = i >> 6, n = i & 63;
            int gn = bn + n;
            Bs[kk][n] = (gn < N) ? B[(size_t)(k0 + kk) * N + gn] : 0.f;
        }
        __syncthreads();
        #pragma unroll
        for (int kk = 0; kk < 16; kk++) {
            float4 a0 = *(const float4*)&As[kk][ty * 8];
            float4 a1 = *(const float4*)&As[kk][ty * 8 + 4];
            float4 b0 = *(const float4*)&Bs[kk][tx * 4];
            float a[8] = {a0.x, a0.y, a0.z, a0.w, a1.x, a1.y, a1.z, a1.w};
            float b[4] = {b0.x, b0.y, b0.z, b0.w};
            #pragma unroll
            for (int i = 0; i < 8; i++)
                #pragma unroll
                for (int j = 0; j < 4; j++)
                    acc[i][j] += a[i] * b[j];
        }
        __syncthreads();
    }

    #pragma unroll
    for (int i = 0; i < 8; i++) {
        int gm = bm + ty * 8 + i;
        if (gm >= M) continue;
        #pragma unroll
        for (int j = 0; j < 4; j++) {
            int gn = bn + tx * 4 + j;
            if (gn < N) g_h[(size_t)gm * N + gn] = acc[i][j];
        }
    }
}

// ---------------------------------------------------------------------------
// CSR build (once per call).  counts start at 1 (self loop per node).
// ---------------------------------------------------------------------------
__global__ void csr_init_cnt(int N) {
    int i = blockIdx.x * blockDim.x + threadIdx.x;
    if (i < N) g_cnt[i] = 1;
}
__global__ void csr_hist(const int* __restrict__ dst, int E) {
    int i = blockIdx.x * blockDim.x + threadIdx.x;
    if (i < E) atomicAdd(&g_cnt[dst[i]], 1);
}
// Single-block scan, shfl-based.  Also writes g_cur[i] = rowptr[i]
// (exclusive prefix = carry + incl - cnt), removing the init_cur kernel.
__global__ void csr_scan(int n) {
    __shared__ int warpsum[32];
    __shared__ int carry;
    int tid = threadIdx.x;           // 1024 threads
    int lane = tid & 31, wid = tid >> 5;
    if (tid == 0) { carry = 0; g_rowptr[0] = 0; }
    __syncthreads();
    for (int base = 0; base < n; base += 1024) {
        int i = base + tid;
        int cnt = (i < n) ? g_cnt[i] : 0;
        int v = cnt;
        #pragma unroll
        for (int off = 1; off < 32; off <<= 1) {
            int t = __shfl_up_sync(0xffffffffu, v, off);
            if (lane >= off) v += t;
        }
        if (lane == 31) warpsum[wid] = v;
        __syncthreads();
        if (wid == 0) {
            int s = warpsum[lane];
            #pragma unroll
            for (int off = 1; off < 32; off <<= 1) {
                int t = __shfl_up_sync(0xffffffffu, s, off);
                if (lane >= off) s += t;
            }
            warpsum[lane] = s;
        }
        __syncthreads();
        int incl = v + ((wid > 0) ? warpsum[wid - 1] : 0);
        if (i < n) {
            g_rowptr[i + 1] = carry + incl;
            g_cur[i] = carry + incl - cnt;   // exclusive prefix = row start
        }
        __syncthreads();                    // all reads of carry done
        if (tid == 1023) carry += warpsum[31];
        __syncthreads();                    // carry visible for next chunk
    }
}
__global__ void csr_scatter(const int* __restrict__ src,
                            const int* __restrict__ dst, int E, int N) {
    int i = blockIdx.x * blockDim.x + threadIdx.x;
    if (i >= E + N) return;
    int s, d;
    if (i < E) { s = src[i]; d = dst[i]; } else { s = d = i - E; }
    int pos = atomicAdd(&g_cur[d], 1);
    g_srcCSR[pos] = s;
}

// ---------------------------------------------------------------------------
// Per-node attention dots, warp per node (H=8, C=64).  Lane -> 16 contiguous
// channels (4 lanes per head): coalesced float4 loads + 4-lane shfl reduce.
// ---------------------------------------------------------------------------
__global__ void node_alpha_wide(const float* __restrict__ a_src,
                                const float* __restrict__ a_dst, int N) {
    int w = (blockIdx.x * blockDim.x + threadIdx.x) >> 5;
    int lane = threadIdx.x & 31;
    if (w >= N) return;
    int hd = lane >> 2, sub = lane & 3;
    const float4* hp = (const float4*)(g_h + (size_t)w * 512 + lane * 16);
    const float4* sp = (const float4*)(a_src + hd * 64 + sub * 16);
    const float4* dp = (const float4*)(a_dst + hd * 64 + sub * 16);
    float s = 0.f, d = 0.f;
    #pragma unroll
    for (int j = 0; j < 4; j++) {
        float4 v = __ldg(hp + j), a = __ldg(sp + j), b = __ldg(dp + j);
        s += v.x * a.x + v.y * a.y + v.z * a.z + v.w * a.w;
        d += v.x * b.x + v.y * b.y + v.z * b.z + v.w * b.w;
    }
    s += __shfl_xor_sync(0xffffffffu, s, 1);
    s += __shfl_xor_sync(0xffffffffu, s, 2);
    d += __shfl_xor_sync(0xffffffffu, d, 1);
    d += __shfl_xor_sync(0xffffffffu, d, 2);
    if (sub == 0) {
        g_als[w * 8 + hd] = s;
        g_ald[w * 8 + hd] = d;
    }
}

// Layer-3 dots (H=1, C=47): small traffic, thread per node.
__global__ void node_alpha_narrow(const float* __restrict__ a_src,
                                  const float* __restrict__ a_dst, int N) {
    int n = blockIdx.x * blockDim.x + threadIdx.x;
    if (n >= N) return;
    const float* hp = g_h + (size_t)n * 47;
    float s = 0.f, d = 0.f;
    #pragma unroll
    for (int c = 0; c < 47; c++) {
        float v = __ldg(hp + c);
        s += v * a_src[c];
        d += v * a_dst[c];
    }
    g_als[n] = s;
    g_ald[n] = d;
}

// ---------------------------------------------------------------------------
// Fused ONLINE softmax + aggregation + epilogue, warp per node (H=8, C=64).
// Single lane-strided sweep maintains per-head (max, den) online; shfl
// combine; then edges sequential, lanes over channels, alpha recomputed from
// a 32B broadcast of als[src].  NEG_BIG (finite) init avoids 0*nan in empty
// lane combines.  No edge buffer.  Read-only streams via __ldg.
// ---------------------------------------------------------------------------
__global__ void gat_edge_wide(const float* __restrict__ bias, int N) {
    int w = (blockIdx.x * blockDim.x + threadIdx.x) >> 5;
    int lane = threadIdx.x & 31;
    if (w >= N) return;
    int row0 = g_rowptr[w], row1 = g_rowptr[w + 1];
    float4 ad0 = __ldg((const float4*)&g_ald[w * 8]);
    float4 ad1 = __ldg((const float4*)&g_ald[w * 8 + 4]);
    float ald[8] = {ad0.x, ad0.y, ad0.z, ad0.w, ad1.x, ad1.y, ad1.z, ad1.w};

    float mx[8], den[8];
    #pragma unroll
    for (int k = 0; k < 8; k++) { mx[k] = NEG_BIG; den[k] = 0.f; }
    for (int i = row0 + lane; i < row1; i += 32) {
        int s = __ldg(&g_srcCSR[i]);
        float4 a0 = __ldg((const float4*)&g_als[s * 8]);
        float4 a1 = __ldg((const float4*)&g_als[s * 8 + 4]);
        float as[8] = {a0.x, a0.y, a0.z, a0.w, a1.x, a1.y, a1.z, a1.w};
        #pragma unroll
        for (int k = 0; k < 8; k++) {
            float v = as[k] + ald[k];
            v = (v > 0.f) ? v : 0.2f * v;
            float mn = fmaxf(mx[k], v);
            den[k] = den[k] * __expf(mx[k] - mn) + __expf(v - mn);
            mx[k] = mn;
        }
    }
    #pragma unroll
    for (int o = 16; o > 0; o >>= 1) {
        #pragma unroll
        for (int k = 0; k < 8; k++) {
            float mo = __shfl_xor_sync(0xffffffffu, mx[k], o);
            float dn = __shfl_xor_sync(0xffffffffu, den[k], o);
            float mn = fmaxf(mx[k], mo);
            den[k] = den[k] * __expf(mx[k] - mn) + dn * __expf(mo - mn);
            mx[k] = mn;
        }
    }

    // Per-lane head values (compare-chain select, no local-mem spill).
    int hd = lane >> 2;
    float mxh  = sel8(mx, hd);
    float aldh = sel8(ald, hd);
    float invh = 1.f / (sel8(den, hd) + 1e-16f);

    int choff = lane * 16;
    float4 acc[4] = {};
    int i = row0;
    for (; i + 1 < row1; i += 2) {
        int s0 = __ldg(&g_srcCSR[i]), s1 = __ldg(&g_srcCSR[i + 1]);
        float e0 = __ldg(&g_als[s0 * 8 + hd]) + aldh;  // 32B sector broadcast
        float e1 = __ldg(&g_als[s1 * 8 + hd]) + aldh;
        e0 = (e0 > 0.f) ? e0 : 0.2f * e0;
        e1 = (e1 > 0.f) ? e1 : 0.2f * e1;
        float al0 = __expf(e0 - mxh);
        float al1 = __expf(e1 - mxh);
        const float4* hp0 = (const float4*)(g_h + (size_t)s0 * 512 + choff);
        const float4* hp1 = (const float4*)(g_h + (size_t)s1 * 512 + choff);
        float4 v0[4], v1[4];
        #pragma unroll
        for (int j = 0; j < 4; j++) { v0[j] = __ldg(hp0 + j); v1[j] = __ldg(hp1 + j); }
        #pragma unroll
        for (int j = 0; j < 4; j++) {
            acc[j].x += al0 * v0[j].x + al1 * v1[j].x;
            acc[j].y += al0 * v0[j].y + al1 * v1[j].y;
            acc[j].z += al0 * v0[j].z + al1 * v1[j].z;
            acc[j].w += al0 * v0[j].w + al1 * v1[j].w;
        }
    }
    if (i < row1) {
        int s = __ldg(&g_srcCSR[i]);
        float e = __ldg(&g_als[s * 8 + hd]) + aldh;
        e = (e > 0.f) ? e : 0.2f * e;
        float al = __expf(e - mxh);
        const float4* hp = (const float4*)(g_h + (size_t)s * 512 + choff);
        #pragma unroll
        for (int j = 0; j < 4; j++) {
            float4 v = __ldg(hp + j);
            acc[j].x += al * v.x;
            acc[j].y += al * v.y;
            acc[j].z += al * v.z;
            acc[j].w += al * v.w;
        }
    }
    const float4* bp = (const float4*)(bias + choff);
    float4* op = (float4*)(g_feat + (size_t)w * 512 + choff);
    #pragma unroll
    for (int j = 0; j < 4; j++) {
        float4 b = __ldg(bp + j);
        op[j] = make_float4(fmaxf(acc[j].x * invh + b.x, 0.f),
                            fmaxf(acc[j].y * invh + b.y, 0.f),
                            fmaxf(acc[j].z * invh + b.z, 0.f),
                            fmaxf(acc[j].w * invh + b.w, 0.f));
    }
}

// Fused layer-3: online softmax + aggregation + bias + log_softmax (H=1,C=47).
__global__ void gat_edge_out(const float* __restrict__ bias,
                             float* __restrict__ out, int N) {
    int w = (blockIdx.x * blockDim.x + threadIdx.x) >> 5;
    int lane = threadIdx.x & 31;
    if (w >= N) return;
    int row0 = g_rowptr[w], row1 = g_rowptr[w + 1];
    float aldn = g_ald[w];

    float mx = NEG_BIG, den = 0.f;
    for (int i = row0 + lane; i < row1; i += 32) {
        float v = __ldg(&g_als[__ldg(&g_srcCSR[i])]) + aldn;
        v = (v > 0.f) ? v : 0.2f * v;
        float mn = fmaxf(mx, v);
        den = den * __expf(mx - mn) + __expf(v - mn);
        mx = mn;
    }
    #pragma unroll
    for (int o = 16; o > 0; o >>= 1) {
        float mo = __shfl_xor_sync(0xffffffffu, mx, o);
        float dn = __shfl_xor_sync(0xffffffffu, den, o);
        float mn = fmaxf(mx, mo);
        den = den * __expf(mx - mn) + dn * __expf(mo - mn);
        mx = mn;
    }
    float inv = 1.f / (den + 1e-16f);

    float acc0 = 0.f, acc1 = 0.f;
    int i = row0;
    for (; i + 1 < row1; i += 2) {
        int s0 = __ldg(&g_srcCSR[i]), s1 = __ldg(&g_srcCSR[i + 1]);
        float e0 = __ldg(&g_als[s0]) + aldn, e1 = __ldg(&g_als[s1]) + aldn;
        e0 = (e0 > 0.f) ? e0 : 0.2f * e0;
        e1 = (e1 > 0.f) ? e1 : 0.2f * e1;
        float al0 = __expf(e0 - mx), al1 = __expf(e1 - mx);
        float h0a = __ldg(&g_h[(size_t)s0 * 47 + lane]);
        float h1a = __ldg(&g_h[(size_t)s1 * 47 + lane]);
        acc0 += al0 * h0a + al1 * h1a;
        if (lane < 15) {
            float h0b = __ldg(&g_h[(size_t)s0 * 47 + lane + 32]);
            float h1b = __ldg(&g_h[(size_t)s1 * 47 + lane + 32]);
            acc1 += al0 * h0b + al1 * h1b;
        }
    }
    if (i < row1) {
        int s = __ldg(&g_srcCSR[i]);
        float e = __ldg(&g_als[s]) + aldn;
        e = (e > 0.f) ? e : 0.2f * e;
        float al = __expf(e - mx);
        acc0 += al * __ldg(&g_h[(size_t)s * 47 + lane]);
        if (lane < 15) acc1 += al * __ldg(&g_h[(size_t)s * 47 + lane + 32]);
    }
    float v1 = acc0 * inv + bias[lane];
    float v2 = (lane < 15) ? acc1 * inv + bias[lane + 32] : -INFINITY;
    float m = fmaxf(v1, v2);
    #pragma unroll
    for (int o = 16; o > 0; o >>= 1) m = fmaxf(m, __shfl_xor_sync(0xffffffffu, m, o));
    float sm = __expf(v1 - m) + ((lane < 15) ? __expf(v2 - m) : 0.f);
    #pragma unroll
    for (int o = 16; o > 0; o >>= 1) sm += __shfl_xor_sync(0xffffffffu, sm, o);
    float lse = m + logf(sm);
    out[(size_t)w * 47 + lane] = v1 - lse;
    if (lane < 15) out[(size_t)w * 47 + lane + 32] = v2 - lse;
}

// ---------------------------------------------------------------------------
extern "C" void kernel_launch(void* const* d_in, const int* in_sizes, int n_in,
                              void* d_out, int out_size) {
    const float* x   = (const float*)d_in[0];
    const int*   ei  = (const int*)d_in[1];
    const float* W1  = (const float*)d_in[2];
    const float* as1 = (const float*)d_in[3];
    const float* ad1 = (const float*)d_in[4];
    const float* b1  = (const float*)d_in[5];
    const float* W2  = (const float*)d_in[6];
    const float* as2 = (const float*)d_in[7];
    const float* ad2 = (const float*)d_in[8];
    const float* b2  = (const float*)d_in[9];
    const float* W3  = (const float*)d_in[10];
    const float* as3 = (const float*)d_in[11];
    const float* ad3 = (const float*)d_in[12];
    const float* b3  = (const float*)d_in[13];
    float* out = (float*)d_out;

    int N = in_sizes[0] / 256;   // 50000
    int E = in_sizes[1] / 2;     // 800000
    const int* srcI = ei;
    const int* dstI = ei + E;

    dim3 grid512(512 / 128, (N + 127) / 128);
    dim3 grid47((47 + 63) / 64, (N + 127) / 128);
    int nodeWarpB = (N + 7) / 8;   // 8 warps (256 thr) per block, warp per node

    // ---- CSR build (graph fixed across layers) ----
    csr_init_cnt<<<(N + 255) / 256, 256>>>(N);
    csr_hist<<<(E + 255) / 256, 256>>>(dstI, E);
    csr_scan<<<1, 1024>>>(N);                 // also writes g_cur
    csr_scatter<<<(E + N + 255) / 256, 256>>>(srcI, dstI, E, N);

    // ---- Layer 1 ----
    gemm128_kernel<<<grid512, 256>>>(x, 0, W1, N, 256, 512);
    node_alpha_wide<<<nodeWarpB, 256>>>(as1, ad1, N);
    gat_edge_wide<<<nodeWarpB, 256>>>(b1, N);

    // ---- Layer 2 ----
    gemm128_kernel<<<grid512, 256>>>(nullptr, 1, W2, N, 512, 512);
    node_alpha_wide<<<nodeWarpB, 256>>>(as2, ad2, N);
    gat_edge_wide<<<nodeWarpB, 256>>>(b2, N);

    // ---- Layer 3 ----
    gemm_small_kernel<<<grid47, 256>>>(W3, N, 512, 47);
    node_alpha_narrow<<<(N + 255) / 256, 256>>>(as3, ad3, N);
    gat_edge_out<<<nodeWarpB, 256>>>(b3, out, N);
}